// round 6
// baseline (speedup 1.0000x reference)
#include <cuda_runtime.h>
#include <cuda_bf16.h>
#include <cstdint>
#include <math.h>

#define N_GENES 10000
#define N_CELLS 8192
#define ZDIM    100
#define KDIM    32
#define HDIM    256

#define NSPLIT  4
#define CPB     (N_CELLS / NSPLIT)           // 2048
#define TC      32
#define NTILES  (CPB / TC)                   // 64
#define GT      128
#define GTILES  ((N_GENES + GT - 1) / GT)    // 79

// ---------------- static device scratch ------------------------------------
__device__ float    d_key[N_CELLS * KDIM];
__device__ uint32_t d_kp[N_CELLS * 32];                    // bf16x2 hi|lo, permuted
__device__ float    d_query[N_GENES * KDIM];
__device__ float    d_zp[(size_t)ZDIM * N_CELLS];          // tf32-rounded, cell-permuted
__device__ float    d_pnum[(size_t)NSPLIT * N_GENES * ZDIM];
__device__ float    d_pden[NSPLIT * N_GENES];

// ---------------- smem layout (bytes) ---------------------------------------
#define SM_K(b)  ((b) * 5120)                // 32 rows x 160B
#define SM_Z(b)  (10240 + (b) * 16640)       // 104 rows x 160B
#define SM_E     43520                       // 128 rows x 160B
#define SMEM_BYTES 64000

__device__ __forceinline__ uint32_t smem_u32(const void* p) {
    uint32_t a;
    asm("{ .reg .u64 t; cvta.to.shared.u64 t, %1; cvt.u32.u64 %0, t; }" : "=r"(a) : "l"(p));
    return a;
}
__device__ __forceinline__ float tf32r(float x) {
    uint32_t u;
    asm("cvt.rna.tf32.f32 %0, %1;" : "=r"(u) : "f"(x));
    return __uint_as_float(u);
}
#define CP_ASYNC16(dst, src) \
    asm volatile("cp.async.cg.shared.global [%0], [%1], 16;" :: "r"(dst), "l"(src))
#define CP_COMMIT() asm volatile("cp.async.commit_group;")
#define CP_WAIT0()  asm volatile("cp.async.wait_group 0;" ::: "memory")

__device__ __forceinline__ void mma_bf16(float c[4],
                                         uint32_t a0, uint32_t a1, uint32_t a2, uint32_t a3,
                                         uint32_t b0, uint32_t b1) {
    asm volatile(
        "mma.sync.aligned.m16n8k16.row.col.f32.bf16.bf16.f32 "
        "{%0,%1,%2,%3}, {%4,%5,%6,%7}, {%8,%9}, {%0,%1,%2,%3};"
        : "+f"(c[0]), "+f"(c[1]), "+f"(c[2]), "+f"(c[3])
        : "r"(a0), "r"(a1), "r"(a2), "r"(a3), "r"(b0), "r"(b1));
}
__device__ __forceinline__ void mma_tf32(float c[4],
                                         uint32_t a0, uint32_t a1, uint32_t a2, uint32_t a3,
                                         uint32_t b0, uint32_t b1) {
    asm volatile(
        "mma.sync.aligned.m16n8k8.row.col.f32.tf32.tf32.f32 "
        "{%0,%1,%2,%3}, {%4,%5,%6,%7}, {%8,%9}, {%0,%1,%2,%3};"
        : "+f"(c[0]), "+f"(c[1]), "+f"(c[2]), "+f"(c[3])
        : "r"(a0), "r"(a1), "r"(a2), "r"(a3), "r"(b0), "r"(b1));
}
__device__ __forceinline__ float2 lds64(uint32_t addr) {
    float2 v;
    asm volatile("ld.shared.v2.f32 {%0,%1}, [%2];" : "=f"(v.x), "=f"(v.y) : "r"(addr));
    return v;
}
__device__ __forceinline__ float gelu_f(float x) {
    return 0.5f * x * (1.0f + erff(x * 0.70710678118654752440f));
}
__device__ __forceinline__ uint32_t pack_bf16(float a, float b) {
    __nv_bfloat162 h = __floats2bfloat162_rn(a, b);
    return *reinterpret_cast<uint32_t*>(&h);
}

// ---------------- K1: key MLP -> d_key[c][k] (fp32) --------------------------
__global__ void __launch_bounds__(256) k_key(
    const float* __restrict__ rawZ,
    const float* __restrict__ Wz1, const float* __restrict__ bz1,
    const float* __restrict__ Wz2, const float* __restrict__ bz2)
{
    __shared__ float Zs[ZDIM * 32];
    __shared__ float hs[HDIM * 33];
    const int t = threadIdx.x;
    const int c0 = blockIdx.x * 32;
    for (int i = t; i < ZDIM * 32; i += 256) {
        int z = i >> 5, c = i & 31;
        Zs[i] = rawZ[(size_t)z * N_CELLS + c0 + c];
    }
    __syncthreads();
    float acc[32];
    {
        float b = bz1[t];
#pragma unroll
        for (int c = 0; c < 32; c++) acc[c] = b;
    }
    for (int z = 0; z < ZDIM; z++) {
        float w = Wz1[z * HDIM + t];
        const float4* zr = reinterpret_cast<const float4*>(&Zs[z * 32]);
#pragma unroll
        for (int u = 0; u < 8; u++) {
            float4 v = zr[u];
            acc[4*u+0] = fmaf(w, v.x, acc[4*u+0]);
            acc[4*u+1] = fmaf(w, v.y, acc[4*u+1]);
            acc[4*u+2] = fmaf(w, v.z, acc[4*u+2]);
            acc[4*u+3] = fmaf(w, v.w, acc[4*u+3]);
        }
    }
#pragma unroll
    for (int c = 0; c < 32; c++) hs[t * 33 + c] = gelu_f(acc[c]);
    __syncthreads();
    const int k = t & 31, cg = t >> 5;
    float a0 = bz2[k], a1 = a0, a2 = a0, a3 = a0;
    for (int h = 0; h < HDIM; h++) {
        float w = Wz2[h * KDIM + k];
        const float* hr = &hs[h * 33 + cg * 4];
        a0 = fmaf(w, hr[0], a0);
        a1 = fmaf(w, hr[1], a1);
        a2 = fmaf(w, hr[2], a2);
        a3 = fmaf(w, hr[3], a3);
    }
    int c = c0 + cg * 4;
    d_key[(size_t)(c + 0) * KDIM + k] = a0;
    d_key[(size_t)(c + 1) * KDIM + k] = a1;
    d_key[(size_t)(c + 2) * KDIM + k] = a2;
    d_key[(size_t)(c + 3) * KDIM + k] = a3;
}

// ---------------- K1b: pack key -> bf16 hi/lo pairs, permuted ----------------
__global__ void k_packK() {
    int tid = blockIdx.x * 256 + threadIdx.x;
    if (tid >= N_CELLS * 16) return;
    int c = tid >> 4, p = tid & 15;
    int ks = p >> 3, j = p & 7;
    int slot = ks * 8 + (j & 3) * 2 + (j >> 2);
    float x0 = d_key[c * 32 + 2 * p], x1 = d_key[c * 32 + 2 * p + 1];
    float h0 = __bfloat162float(__float2bfloat16(x0));
    float h1 = __bfloat162float(__float2bfloat16(x1));
    d_kp[c * 32 + slot]      = pack_bf16(h0, h1);
    d_kp[c * 32 + 16 + slot] = pack_bf16(x0 - h0, x1 - h1);
}

// ---------------- K0: genZ -> tf32-rounded, cell-permuted --------------------
__global__ void k_packZ(const float* __restrict__ genZ) {
    int tid = blockIdx.x * 256 + threadIdx.x;
    if (tid >= ZDIM * N_CELLS) return;
    int z = tid >> 13, c = tid & 8191;
    int j = c & 7;
    int cp = (c & ~7) + (j & 3) * 2 + (j >> 2);
    d_zp[(size_t)z * N_CELLS + cp] = tf32r(genZ[tid]);
}

// ---------------- K2: query MLP -> d_query[g][k] ----------------------------
__global__ void k_query(
    const float* __restrict__ Grep,
    const float* __restrict__ Wg1, const float* __restrict__ bg1,
    const float* __restrict__ Wg2, const float* __restrict__ bg2)
{
    int gene = blockIdx.x * 8 + (threadIdx.x >> 5);
    int k = threadIdx.x & 31;
    if (gene >= N_GENES) return;
    const float* grow = &Grep[(size_t)gene * 100];
    float h0 = 0.f, h1 = 0.f, h2 = 0.f, h3 = 0.f;
#pragma unroll
    for (int j = 0; j < 100; j += 4) {
        h0 = fmaf(grow[j + 0], Wg1[(j + 0) * 32 + k], h0);
        h1 = fmaf(grow[j + 1], Wg1[(j + 1) * 32 + k], h1);
        h2 = fmaf(grow[j + 2], Wg1[(j + 2) * 32 + k], h2);
        h3 = fmaf(grow[j + 3], Wg1[(j + 3) * 32 + k], h3);
    }
    float h = gelu_f(((h0 + h1) + (h2 + h3)) + bg1[k]);
    float q = bg2[k];
#pragma unroll
    for (int j = 0; j < 32; j++) {
        float hj = __shfl_sync(0xffffffffu, h, j);
        q = fmaf(hj, Wg2[j * 32 + k], q);
    }
    d_query[(size_t)gene * KDIM + k] = q;
}

// ---------------- K3: fused flash attention (4 warps, 32 genes/warp) ---------
__global__ void __launch_bounds__(128, 2) k_attn(const float* __restrict__ gumbel) {
    extern __shared__ __align__(16) char smem[];
    const uint32_t sb = smem_u32(smem);
    const int t = threadIdx.x;
    const int w = t >> 5, lane = t & 31;
    const int quad = lane >> 2, qi = lane & 3;
    const int g0 = blockIdx.x * GT;
    const int s = blockIdx.y;
    const int cbase = s * CPB;
    const int wg0 = w * 32;                  // warp owns E rows wg0..wg0+31
    const float SC = 0.17677669529663687f;

    // ---- Q a-frags for both m-blocks (bf16 hi/lo), genes validity ----
    uint32_t aQh[2][2][4], aQl[2][2][4];
    bool okr[2][2];
#pragma unroll
    for (int mb = 0; mb < 2; mb++) {
        int gbase = g0 + wg0 + mb * 16 + quad;
        okr[mb][0] = gbase < N_GENES;
        okr[mb][1] = gbase + 8 < N_GENES;
#pragma unroll
        for (int ks = 0; ks < 2; ks++) {
#pragma unroll
            for (int r = 0; r < 4; r++) {
                int gg = gbase + ((r & 1) ? 8 : 0);
                int kk = ks * 16 + 2 * qi + ((r & 2) ? 8 : 0);
                float x0 = 0.f, x1 = 0.f;
                if (okr[mb][r & 1]) {
                    float2 v = *reinterpret_cast<const float2*>(&d_query[(size_t)gg * 32 + kk]);
                    x0 = v.x; x1 = v.y;
                }
                float h0 = __bfloat162float(__float2bfloat16(x0));
                float h1 = __bfloat162float(__float2bfloat16(x1));
                aQh[mb][ks][r] = pack_bf16(h0, h1);
                aQl[mb][ks][r] = pack_bf16(x0 - h0, x1 - h1);
            }
        }
    }

    // ---- constant Z rows 100..103 in both buffers ----
    {
        int z = 100 + w, c = lane;
        float v = (z == 100) ? 1.0f : 0.0f;
        *reinterpret_cast<float*>(smem + SM_Z(0) + z * 160 + c * 4) = v;
        *reinterpret_cast<float*>(smem + SM_Z(1) + z * 160 + c * 4) = v;
    }

    // ---- cp.async tile 0 ----
    {
        for (int idx = t; idx < 256; idx += 128) {
            int row = idx >> 3, ch = idx & 7;
            CP_ASYNC16(sb + SM_K(0) + row * 160 + ch * 16,
                       (const char*)(d_kp + (size_t)(cbase + row) * 32 + ch * 4));
        }
        for (int idx = t; idx < 800; idx += 128) {
            int zr = idx >> 3, zc = idx & 7;
            CP_ASYNC16(sb + SM_Z(0) + zr * 160 + zc * 16,
                       (const char*)(d_zp + (size_t)zr * N_CELLS + cbase + zc * 4));
        }
    }
    CP_COMMIT();
    CP_WAIT0();
    __syncthreads();

    float O[2][13][4];
#pragma unroll
    for (int mb = 0; mb < 2; mb++)
#pragma unroll
        for (int nt = 0; nt < 13; nt++)
#pragma unroll
            for (int e = 0; e < 4; e++) O[mb][nt][e] = 0.0f;

    const int pos0 = (qi & 1) * 4 + (qi >> 1);   // permuted slot of cell 2qi

    for (int i = 0; i < NTILES; i++) {
        const int b = i & 1, nb = b ^ 1;
        const int c0 = cbase + i * TC;

        // prefetch tile i+1
        if (i + 1 < NTILES) {
            int c1 = c0 + TC;
            for (int idx = t; idx < 256; idx += 128) {
                int row = idx >> 3, ch = idx & 7;
                CP_ASYNC16(sb + SM_K(nb) + row * 160 + ch * 16,
                           (const char*)(d_kp + (size_t)(c1 + row) * 32 + ch * 4));
            }
            for (int idx = t; idx < 800; idx += 128) {
                int zr = idx >> 3, zc = idx & 7;
                CP_ASYNC16(sb + SM_Z(nb) + zr * 160 + zc * 16,
                           (const char*)(d_zp + (size_t)zr * N_CELLS + c1 + zc * 4));
            }
        }
        CP_COMMIT();

        const uint32_t kbase = sb + SM_K(b);
        const uint32_t ebase = sb + SM_E;

        // ---- per m-block: gumbel, MMA1 (3-product bf16), exp, store E ----
#pragma unroll
        for (int mb = 0; mb < 2; mb++) {
            const int gene0 = g0 + wg0 + mb * 16 + quad;
            const int gene1 = gene0 + 8;

            float2 gv0[4], gv1[4];
#pragma unroll
            for (int nt = 0; nt < 4; nt++) {
                gv0[nt] = okr[mb][0] ? __ldcs(reinterpret_cast<const float2*>(
                              &gumbel[(size_t)gene0 * N_CELLS + c0 + nt * 8 + 2 * qi]))
                              : make_float2(0.f, 0.f);
                gv1[nt] = okr[mb][1] ? __ldcs(reinterpret_cast<const float2*>(
                              &gumbel[(size_t)gene1 * N_CELLS + c0 + nt * 8 + 2 * qi]))
                              : make_float2(0.f, 0.f);
            }

            float C[8][4];
#pragma unroll
            for (int m = 0; m < 8; m++)
#pragma unroll
                for (int e = 0; e < 4; e++) C[m][e] = 0.0f;

#pragma unroll
            for (int p = 0; p < 3; p++) {
                // p==0: Qh*Kh ; p==1: Ql*Kh ; p==2: Qh*Kl
                const uint32_t hl = (p == 2) ? 64u : 0u;
#pragma unroll
                for (int ks = 0; ks < 2; ks++) {
                    const uint32_t* aa = (p == 1) ? aQl[mb][ks] : aQh[mb][ks];
#pragma unroll
                    for (int nt = 0; nt < 4; nt++) {
                        uint32_t addr = kbase + (nt * 8 + quad) * 160 + (ks * 4 + qi) * 8 + hl;
                        float2 bb = lds64(addr);
                        mma_bf16(C[ks * 4 + nt], aa[0], aa[1], aa[2], aa[3],
                                 __float_as_uint(bb.x), __float_as_uint(bb.y));
                    }
                }
            }

#pragma unroll
            for (int nt = 0; nt < 4; nt++) {
                float d0 = C[nt][0] + C[4 + nt][0];
                float d1 = C[nt][1] + C[4 + nt][1];
                float d2 = C[nt][2] + C[4 + nt][2];
                float d3 = C[nt][3] + C[4 + nt][3];
                float e0 = tf32r(__expf(fmaf(d0, SC, gv0[nt].x)));
                float e1 = tf32r(__expf(fmaf(d1, SC, gv0[nt].y)));
                float e2 = tf32r(__expf(fmaf(d2, SC, gv1[nt].x)));
                float e3 = tf32r(__expf(fmaf(d3, SC, gv1[nt].y)));
                uint32_t r0 = ebase + (wg0 + mb * 16 + quad) * 160 + (nt * 8 + pos0) * 4;
                uint32_t r1 = ebase + (wg0 + mb * 16 + quad + 8) * 160 + (nt * 8 + pos0) * 4;
                asm volatile("st.shared.f32 [%0], %1;" :: "r"(r0), "f"(e0));
                asm volatile("st.shared.f32 [%0], %1;" :: "r"(r0 + 8), "f"(e1));
                asm volatile("st.shared.f32 [%0], %1;" :: "r"(r1), "f"(e2));
                asm volatile("st.shared.f32 [%0], %1;" :: "r"(r1 + 8), "f"(e3));
            }
        }
        __syncwarp();

        // ---- MMA2: O[mb] += E(tf32) * Z(tf32), Z frags shared by both mb ----
        const uint32_t zbase = sb + SM_Z(b);
#pragma unroll
        for (int ks = 0; ks < 4; ks++) {
            float2 ae02_0 = lds64(ebase + (wg0 + quad) * 160 + (ks * 4 + qi) * 8);
            float2 ae13_0 = lds64(ebase + (wg0 + quad + 8) * 160 + (ks * 4 + qi) * 8);
            float2 ae02_1 = lds64(ebase + (wg0 + 16 + quad) * 160 + (ks * 4 + qi) * 8);
            float2 ae13_1 = lds64(ebase + (wg0 + 16 + quad + 8) * 160 + (ks * 4 + qi) * 8);
            uint32_t a00 = __float_as_uint(ae02_0.x), a20 = __float_as_uint(ae02_0.y);
            uint32_t a10 = __float_as_uint(ae13_0.x), a30 = __float_as_uint(ae13_0.y);
            uint32_t a01 = __float_as_uint(ae02_1.x), a21 = __float_as_uint(ae02_1.y);
            uint32_t a11 = __float_as_uint(ae13_1.x), a31 = __float_as_uint(ae13_1.y);
#pragma unroll
            for (int nt = 0; nt < 13; nt++) {
                float2 bz = lds64(zbase + (nt * 8 + quad) * 160 + (ks * 4 + qi) * 8);
                uint32_t bz0 = __float_as_uint(bz.x), bz1 = __float_as_uint(bz.y);
                mma_tf32(O[0][nt], a00, a10, a20, a30, bz0, bz1);
                mma_tf32(O[1][nt], a01, a11, a21, a31, bz0, bz1);
            }
        }

        CP_WAIT0();
        __syncthreads();
    }

    // ---- epilogue ----
#pragma unroll
    for (int mb = 0; mb < 2; mb++) {
#pragma unroll
        for (int half = 0; half < 2; half++) {
            int g = g0 + wg0 + mb * 16 + quad + half * 8;
            if (g >= N_GENES) continue;
            float* base = &d_pnum[((size_t)s * N_GENES + g) * ZDIM];
#pragma unroll
            for (int nt = 0; nt < 12; nt++)
                *reinterpret_cast<float2*>(&base[nt * 8 + 2 * qi]) =
                    make_float2(O[mb][nt][half * 2 + 0], O[mb][nt][half * 2 + 1]);
            int col = 96 + 2 * qi;
            if (col < 100)
                *reinterpret_cast<float2*>(&base[col]) =
                    make_float2(O[mb][12][half * 2 + 0], O[mb][12][half * 2 + 1]);
            else if (col == 100)
                d_pden[s * N_GENES + g] = O[mb][12][half * 2 + 0];
        }
    }
}

// ---------------- K4: combine + normalize + transpose -----------------------
__global__ void k_combine(float* __restrict__ out) {
    int t = blockIdx.x * 256 + threadIdx.x;
    if (t >= N_GENES * ZDIM) return;
    int g = t / ZDIM, z = t % ZDIM;
    float num = 0.f, den = 0.f;
#pragma unroll
    for (int sp = 0; sp < NSPLIT; sp++) {
        num += d_pnum[((size_t)sp * N_GENES + g) * ZDIM + z];
        den += d_pden[sp * N_GENES + g];
    }
    out[(size_t)z * N_GENES + g] = num / den;
}

// ---------------- launch ------------------------------------------------------
extern "C" void kernel_launch(void* const* d_in, const int* in_sizes, int n_in,
                              void* d_out, int out_size) {
    (void)in_sizes; (void)n_in; (void)out_size;
    const float* rawZ   = (const float*)d_in[0];
    const float* genZ   = (const float*)d_in[1];
    const float* Grep   = (const float*)d_in[2];
    const float* gumbel = (const float*)d_in[3];
    const float* Wz1    = (const float*)d_in[4];
    const float* bz1    = (const float*)d_in[5];
    const float* Wz2    = (const float*)d_in[6];
    const float* bz2    = (const float*)d_in[7];
    const float* Wg1    = (const float*)d_in[8];
    const float* bg1    = (const float*)d_in[9];
    const float* Wg2    = (const float*)d_in[10];
    const float* bg2    = (const float*)d_in[11];
    float* out = (float*)d_out;

    static bool configured = false;
    if (!configured) {
        cudaFuncSetAttribute(k_attn, cudaFuncAttributeMaxDynamicSharedMemorySize, SMEM_BYTES);
        configured = true;
    }

    k_key<<<N_CELLS / 32, 256>>>(rawZ, Wz1, bz1, Wz2, bz2);
    k_packK<<<(N_CELLS * 16 + 255) / 256, 256>>>();
    k_packZ<<<(ZDIM * N_CELLS + 255) / 256, 256>>>(genZ);
    k_query<<<(N_GENES + 7) / 8, 256>>>(Grep, Wg1, bg1, Wg2, bg2);
    k_attn<<<dim3(GTILES, NSPLIT), 128, SMEM_BYTES>>>(gumbel);
    k_combine<<<(N_GENES * ZDIM + 255) / 256, 256>>>(out);
}

// round 7
// speedup vs baseline: 1.3713x; 1.3713x over previous
#include <cuda_runtime.h>
#include <cuda_bf16.h>
#include <cstdint>
#include <math.h>

#define N_GENES 10000
#define N_CELLS 8192
#define ZDIM    100
#define KDIM    32
#define HDIM    256

#define NSPLIT  4
#define CPB     (N_CELLS / NSPLIT)           // 2048
#define TC      32
#define NTILES  (CPB / TC)                   // 64
#define GT      128
#define GTILES  ((N_GENES + GT - 1) / GT)    // 79

// ---------------- static device scratch ------------------------------------
__device__ float    d_key[N_CELLS * KDIM];
__device__ uint32_t d_kp[N_CELLS * 32];            // [cell][(ks*4+q)*4 + {hib0,hib1,lob0,lob1}]
__device__ float    d_query[N_GENES * KDIM];
__device__ float    d_zp[(size_t)ZDIM * N_CELLS];  // tf32, kp-paired permutation
__device__ float    d_pnum[(size_t)NSPLIT * N_GENES * ZDIM];
__device__ float    d_pden[NSPLIT * N_GENES];

// ---------------- smem layout (bytes) ---------------------------------------
// K tiles: 32 rows x 192B (128B data)   -> 6144 each
// Z tiles: 104 rows x 192B (128B data)  -> 19968 each
// E:       128 rows x 160B              -> 20480
#define SM_K(b)  ((b) * 6144)
#define SM_Z(b)  (12288 + (b) * 19968)
#define SM_E     52224
#define SMEM_BYTES 72704

__device__ __forceinline__ uint32_t smem_u32(const void* p) {
    uint32_t a;
    asm("{ .reg .u64 t; cvta.to.shared.u64 t, %1; cvt.u32.u64 %0, t; }" : "=r"(a) : "l"(p));
    return a;
}
__device__ __forceinline__ float tf32r(float x) {
    uint32_t u;
    asm("cvt.rna.tf32.f32 %0, %1;" : "=r"(u) : "f"(x));
    return __uint_as_float(u);
}
#define CP_ASYNC16(dst, src) \
    asm volatile("cp.async.cg.shared.global [%0], [%1], 16;" :: "r"(dst), "l"(src))
#define CP_COMMIT() asm volatile("cp.async.commit_group;")
#define CP_WAIT0()  asm volatile("cp.async.wait_group 0;" ::: "memory")

__device__ __forceinline__ void mma_bf16(float c[4],
                                         uint32_t a0, uint32_t a1, uint32_t a2, uint32_t a3,
                                         uint32_t b0, uint32_t b1) {
    asm volatile(
        "mma.sync.aligned.m16n8k16.row.col.f32.bf16.bf16.f32 "
        "{%0,%1,%2,%3}, {%4,%5,%6,%7}, {%8,%9}, {%0,%1,%2,%3};"
        : "+f"(c[0]), "+f"(c[1]), "+f"(c[2]), "+f"(c[3])
        : "r"(a0), "r"(a1), "r"(a2), "r"(a3), "r"(b0), "r"(b1));
}
__device__ __forceinline__ void mma_tf32(float c[4],
                                         uint32_t a0, uint32_t a1, uint32_t a2, uint32_t a3,
                                         uint32_t b0, uint32_t b1) {
    asm volatile(
        "mma.sync.aligned.m16n8k8.row.col.f32.tf32.tf32.f32 "
        "{%0,%1,%2,%3}, {%4,%5,%6,%7}, {%8,%9}, {%0,%1,%2,%3};"
        : "+f"(c[0]), "+f"(c[1]), "+f"(c[2]), "+f"(c[3])
        : "r"(a0), "r"(a1), "r"(a2), "r"(a3), "r"(b0), "r"(b1));
}
__device__ __forceinline__ float2 lds64(uint32_t addr) {
    float2 v;
    asm volatile("ld.shared.v2.f32 {%0,%1}, [%2];" : "=f"(v.x), "=f"(v.y) : "r"(addr));
    return v;
}
__device__ __forceinline__ uint4 lds128(uint32_t addr) {
    uint4 v;
    asm volatile("ld.shared.v4.u32 {%0,%1,%2,%3}, [%4];"
                 : "=r"(v.x), "=r"(v.y), "=r"(v.z), "=r"(v.w) : "r"(addr));
    return v;
}
__device__ __forceinline__ float gelu_f(float x) {
    return 0.5f * x * (1.0f + erff(x * 0.70710678118654752440f));
}
__device__ __forceinline__ uint32_t pack_bf16(float a, float b) {
    __nv_bfloat162 h = __floats2bfloat162_rn(a, b);
    return *reinterpret_cast<uint32_t*>(&h);
}

// ---------------- K1: key MLP -> d_key[c][k] (fp32) --------------------------
__global__ void __launch_bounds__(256) k_key(
    const float* __restrict__ rawZ,
    const float* __restrict__ Wz1, const float* __restrict__ bz1,
    const float* __restrict__ Wz2, const float* __restrict__ bz2)
{
    __shared__ float Zs[ZDIM * 32];
    __shared__ float hs[HDIM * 33];
    const int t = threadIdx.x;
    const int c0 = blockIdx.x * 32;
    for (int i = t; i < ZDIM * 32; i += 256) {
        int z = i >> 5, c = i & 31;
        Zs[i] = rawZ[(size_t)z * N_CELLS + c0 + c];
    }
    __syncthreads();
    float acc[32];
    {
        float b = bz1[t];
#pragma unroll
        for (int c = 0; c < 32; c++) acc[c] = b;
    }
    for (int z = 0; z < ZDIM; z++) {
        float w = Wz1[z * HDIM + t];
        const float4* zr = reinterpret_cast<const float4*>(&Zs[z * 32]);
#pragma unroll
        for (int u = 0; u < 8; u++) {
            float4 v = zr[u];
            acc[4*u+0] = fmaf(w, v.x, acc[4*u+0]);
            acc[4*u+1] = fmaf(w, v.y, acc[4*u+1]);
            acc[4*u+2] = fmaf(w, v.z, acc[4*u+2]);
            acc[4*u+3] = fmaf(w, v.w, acc[4*u+3]);
        }
    }
#pragma unroll
    for (int c = 0; c < 32; c++) hs[t * 33 + c] = gelu_f(acc[c]);
    __syncthreads();
    const int k = t & 31, cg = t >> 5;
    float a0 = bz2[k], a1 = a0, a2 = a0, a3 = a0;
    for (int h = 0; h < HDIM; h++) {
        float w = Wz2[h * KDIM + k];
        const float* hr = &hs[h * 33 + cg * 4];
        a0 = fmaf(w, hr[0], a0);
        a1 = fmaf(w, hr[1], a1);
        a2 = fmaf(w, hr[2], a2);
        a3 = fmaf(w, hr[3], a3);
    }
    int c = c0 + cg * 4;
    d_key[(size_t)(c + 0) * KDIM + k] = a0;
    d_key[(size_t)(c + 1) * KDIM + k] = a1;
    d_key[(size_t)(c + 2) * KDIM + k] = a2;
    d_key[(size_t)(c + 3) * KDIM + k] = a3;
}

// ---------------- K1b: pack key -> bf16 hi/lo adjacent quads -----------------
// For kdim-pair p (0..15): ks=p>>3, j=p&7, q=j&3, h=j>>2.
// hi -> d_kp[c*32 + (ks*4+q)*4 + h], lo -> +2.
__global__ void k_packK() {
    int tid = blockIdx.x * 256 + threadIdx.x;
    if (tid >= N_CELLS * 16) return;
    int c = tid >> 4, p = tid & 15;
    int ks = p >> 3, j = p & 7, q = j & 3, h = j >> 2;
    float x0 = d_key[c * 32 + 2 * p], x1 = d_key[c * 32 + 2 * p + 1];
    float h0 = __bfloat162float(__float2bfloat16(x0));
    float h1 = __bfloat162float(__float2bfloat16(x1));
    int base = c * 32 + (ks * 4 + q) * 4 + h;
    d_kp[base]     = pack_bf16(h0, h1);
    d_kp[base + 2] = pack_bf16(x0 - h0, x1 - h1);
}

// ---------------- K0: genZ -> tf32, kp-paired permutation --------------------
// cell c within 32-group: ks=c>>3, j=c&7 -> pos = (ks>>1)*16 + (j&3)*4 + (ks&1)*2 + (j>>2)
__global__ void k_packZ(const float* __restrict__ genZ) {
    int tid = blockIdx.x * 256 + threadIdx.x;
    if (tid >= ZDIM * N_CELLS) return;
    int z = tid >> 13, c = tid & 8191;
    int w = c & 31, ks = w >> 3, j = w & 7;
    int pos = (ks >> 1) * 16 + (j & 3) * 4 + (ks & 1) * 2 + (j >> 2);
    d_zp[(size_t)z * N_CELLS + (c & ~31) + pos] = tf32r(genZ[tid]);
}

// ---------------- K2: query MLP -> d_query[g][k] ----------------------------
__global__ void k_query(
    const float* __restrict__ Grep,
    const float* __restrict__ Wg1, const float* __restrict__ bg1,
    const float* __restrict__ Wg2, const float* __restrict__ bg2)
{
    int gene = blockIdx.x * 8 + (threadIdx.x >> 5);
    int k = threadIdx.x & 31;
    if (gene >= N_GENES) return;
    const float* grow = &Grep[(size_t)gene * 100];
    float h0 = 0.f, h1 = 0.f, h2 = 0.f, h3 = 0.f;
#pragma unroll
    for (int j = 0; j < 100; j += 4) {
        h0 = fmaf(grow[j + 0], Wg1[(j + 0) * 32 + k], h0);
        h1 = fmaf(grow[j + 1], Wg1[(j + 1) * 32 + k], h1);
        h2 = fmaf(grow[j + 2], Wg1[(j + 2) * 32 + k], h2);
        h3 = fmaf(grow[j + 3], Wg1[(j + 3) * 32 + k], h3);
    }
    float h = gelu_f(((h0 + h1) + (h2 + h3)) + bg1[k]);
    float q = bg2[k];
#pragma unroll
    for (int j = 0; j < 32; j++) {
        float hj = __shfl_sync(0xffffffffu, h, j);
        q = fmaf(hj, Wg2[j * 32 + k], q);
    }
    d_query[(size_t)gene * KDIM + k] = q;
}

// ---------------- K3: fused flash attention (8 warps, 16 genes/warp) ---------
__global__ void __launch_bounds__(256, 2) k_attn(const float* __restrict__ gumbel) {
    extern __shared__ __align__(16) char smem[];
    const uint32_t sb = smem_u32(smem);
    const int t = threadIdx.x;
    const int w = t >> 5, lane = t & 31;
    const int quad = lane >> 2, qi = lane & 3;
    const int g0 = blockIdx.x * GT;
    const int s = blockIdx.y;
    const int cbase = s * CPB;
    const int wg0 = w * 16;
    const int gene0 = g0 + wg0 + quad;
    const int gene1 = gene0 + 8;
    const bool ok0 = gene0 < N_GENES, ok1 = gene1 < N_GENES;
    const float SC = 0.17677669529663687f;

    // ---- Q a-frags (bf16 hi/lo) in registers ----
    uint32_t aQh[2][4], aQl[2][4];
#pragma unroll
    for (int ks = 0; ks < 2; ks++) {
#pragma unroll
        for (int r = 0; r < 4; r++) {
            int gg = (r & 1) ? gene1 : gene0;
            int kk = ks * 16 + 2 * qi + ((r & 2) ? 8 : 0);
            float x0 = 0.f, x1 = 0.f;
            if ((r & 1) ? ok1 : ok0) {
                float2 v = *reinterpret_cast<const float2*>(&d_query[(size_t)gg * 32 + kk]);
                x0 = v.x; x1 = v.y;
            }
            float h0 = __bfloat162float(__float2bfloat16(x0));
            float h1 = __bfloat162float(__float2bfloat16(x1));
            aQh[ks][r] = pack_bf16(h0, h1);
            aQl[ks][r] = pack_bf16(x0 - h0, x1 - h1);
        }
    }

    // ---- constant Z rows 100..103 in both buffers ----
    if (t < 128) {
        int z = 100 + (t >> 5), c = t & 31;
        float v = (z == 100) ? 1.0f : 0.0f;
        *reinterpret_cast<float*>(smem + SM_Z(0) + z * 192 + c * 4) = v;
        *reinterpret_cast<float*>(smem + SM_Z(1) + z * 192 + c * 4) = v;
    }

    // ---- cp.async tile 0 ----
    {
        int row = t >> 3, ch = t & 7;
        CP_ASYNC16(sb + SM_K(0) + row * 192 + ch * 16,
                   (const char*)(d_kp + (size_t)(cbase + row) * 32 + ch * 4));
        for (int idx = t; idx < 800; idx += 256) {
            int zr = idx >> 3, zc = idx & 7;
            CP_ASYNC16(sb + SM_Z(0) + zr * 192 + zc * 16,
                       (const char*)(d_zp + (size_t)zr * N_CELLS + cbase + zc * 4));
        }
    }
    CP_COMMIT();
    CP_WAIT0();
    __syncthreads();

    float O[13][4];
#pragma unroll
    for (int nt = 0; nt < 13; nt++)
#pragma unroll
        for (int e = 0; e < 4; e++) O[nt][e] = 0.0f;

    const int pos0 = (qi & 1) * 4 + (qi >> 1);   // E slot of cell 2qi (R5 layout)

    for (int i = 0; i < NTILES; i++) {
        const int b = i & 1, nb = b ^ 1;
        const int c0 = cbase + i * TC;

        // prefetch tile i+1
        if (i + 1 < NTILES) {
            int c1 = c0 + TC;
            int row = t >> 3, ch = t & 7;
            CP_ASYNC16(sb + SM_K(nb) + row * 192 + ch * 16,
                       (const char*)(d_kp + (size_t)(c1 + row) * 32 + ch * 4));
            for (int idx = t; idx < 800; idx += 256) {
                int zr = idx >> 3, zc = idx & 7;
                CP_ASYNC16(sb + SM_Z(nb) + zr * 192 + zc * 16,
                           (const char*)(d_zp + (size_t)zr * N_CELLS + c1 + zc * 4));
            }
        }
        CP_COMMIT();

        // gumbel prefetch (this tile), streaming
        float2 gv0[4], gv1[4];
#pragma unroll
        for (int nt = 0; nt < 4; nt++) {
            gv0[nt] = ok0 ? __ldcs(reinterpret_cast<const float2*>(
                          &gumbel[(size_t)gene0 * N_CELLS + c0 + nt * 8 + 2 * qi]))
                          : make_float2(0.f, 0.f);
            gv1[nt] = ok1 ? __ldcs(reinterpret_cast<const float2*>(
                          &gumbel[(size_t)gene1 * N_CELLS + c0 + nt * 8 + 2 * qi]))
                          : make_float2(0.f, 0.f);
        }

        // ---- MMA1: scores, 3-product bf16, LDS.128 hi/lo-paired frags ----
        float C[4][4];
#pragma unroll
        for (int m = 0; m < 4; m++)
#pragma unroll
            for (int e = 0; e < 4; e++) C[m][e] = 0.0f;

        const uint32_t kbase = sb + SM_K(b);
#pragma unroll
        for (int ks = 0; ks < 2; ks++) {
            uint4 kb0 = lds128(kbase + (0 * 8 + quad) * 192 + (ks * 4 + qi) * 16);
            uint4 kb1 = lds128(kbase + (1 * 8 + quad) * 192 + (ks * 4 + qi) * 16);
            uint4 kb2 = lds128(kbase + (2 * 8 + quad) * 192 + (ks * 4 + qi) * 16);
            uint4 kb3 = lds128(kbase + (3 * 8 + quad) * 192 + (ks * 4 + qi) * 16);
            const uint32_t* ah = aQh[ks];
            const uint32_t* al = aQl[ks];
            mma_bf16(C[0], ah[0], ah[1], ah[2], ah[3], kb0.x, kb0.y);
            mma_bf16(C[1], ah[0], ah[1], ah[2], ah[3], kb1.x, kb1.y);
            mma_bf16(C[2], ah[0], ah[1], ah[2], ah[3], kb2.x, kb2.y);
            mma_bf16(C[3], ah[0], ah[1], ah[2], ah[3], kb3.x, kb3.y);
            mma_bf16(C[0], al[0], al[1], al[2], al[3], kb0.x, kb0.y);
            mma_bf16(C[1], al[0], al[1], al[2], al[3], kb1.x, kb1.y);
            mma_bf16(C[2], al[0], al[1], al[2], al[3], kb2.x, kb2.y);
            mma_bf16(C[3], al[0], al[1], al[2], al[3], kb3.x, kb3.y);
            mma_bf16(C[0], ah[0], ah[1], ah[2], ah[3], kb0.z, kb0.w);
            mma_bf16(C[1], ah[0], ah[1], ah[2], ah[3], kb1.z, kb1.w);
            mma_bf16(C[2], ah[0], ah[1], ah[2], ah[3], kb2.z, kb2.w);
            mma_bf16(C[3], ah[0], ah[1], ah[2], ah[3], kb3.z, kb3.w);
        }

        // ---- exp + gumbel -> E (tf32) into smem (R5 layout, 160B rows) ----
        const uint32_t ebase = sb + SM_E;
#pragma unroll
        for (int nt = 0; nt < 4; nt++) {
            float e0 = tf32r(__expf(fmaf(C[nt][0], SC, gv0[nt].x)));
            float e1 = tf32r(__expf(fmaf(C[nt][1], SC, gv0[nt].y)));
            float e2 = tf32r(__expf(fmaf(C[nt][2], SC, gv1[nt].x)));
            float e3 = tf32r(__expf(fmaf(C[nt][3], SC, gv1[nt].y)));
            uint32_t r0 = ebase + (wg0 + quad) * 160 + (nt * 8 + pos0) * 4;
            uint32_t r1 = ebase + (wg0 + quad + 8) * 160 + (nt * 8 + pos0) * 4;
            asm volatile("st.shared.f32 [%0], %1;" :: "r"(r0), "f"(e0));
            asm volatile("st.shared.f32 [%0], %1;" :: "r"(r0 + 8), "f"(e1));
            asm volatile("st.shared.f32 [%0], %1;" :: "r"(r1), "f"(e2));
            asm volatile("st.shared.f32 [%0], %1;" :: "r"(r1 + 8), "f"(e3));
        }
        __syncwarp();

        // ---- MMA2: O += E(tf32) * Z(tf32); Z frags LDS.128 ks-paired ----
        const uint32_t zbase = sb + SM_Z(b);
#pragma unroll
        for (int kp = 0; kp < 2; kp++) {
            // E a-frags for ks_e = 2kp, ks_o = 2kp+1 (R5 E layout)
            float2 e_e02 = lds64(ebase + (wg0 + quad) * 160 + ((2 * kp) * 4 + qi) * 8);
            float2 e_e13 = lds64(ebase + (wg0 + quad + 8) * 160 + ((2 * kp) * 4 + qi) * 8);
            float2 e_o02 = lds64(ebase + (wg0 + quad) * 160 + ((2 * kp + 1) * 4 + qi) * 8);
            float2 e_o13 = lds64(ebase + (wg0 + quad + 8) * 160 + ((2 * kp + 1) * 4 + qi) * 8);
            uint32_t ea0 = __float_as_uint(e_e02.x), ea2 = __float_as_uint(e_e02.y);
            uint32_t ea1 = __float_as_uint(e_e13.x), ea3 = __float_as_uint(e_e13.y);
            uint32_t oa0 = __float_as_uint(e_o02.x), oa2 = __float_as_uint(e_o02.y);
            uint32_t oa1 = __float_as_uint(e_o13.x), oa3 = __float_as_uint(e_o13.y);

            const uint32_t zoff = kp * 64 + qi * 16;
#pragma unroll
            for (int nt = 0; nt < 12; nt += 2) {
                uint4 z0 = lds128(zbase + ((nt + 0) * 8 + quad) * 192 + zoff);
                uint4 z1 = lds128(zbase + ((nt + 1) * 8 + quad) * 192 + zoff);
                mma_tf32(O[nt + 0], ea0, ea1, ea2, ea3, z0.x, z0.y);
                mma_tf32(O[nt + 1], ea0, ea1, ea2, ea3, z1.x, z1.y);
                mma_tf32(O[nt + 0], oa0, oa1, oa2, oa3, z0.z, z0.w);
                mma_tf32(O[nt + 1], oa0, oa1, oa2, oa3, z1.z, z1.w);
            }
            {   // tail nt = 12
                uint4 z0 = lds128(zbase + (12 * 8 + quad) * 192 + zoff);
                mma_tf32(O[12], ea0, ea1, ea2, ea3, z0.x, z0.y);
                mma_tf32(O[12], oa0, oa1, oa2, oa3, z0.z, z0.w);
            }
        }

        CP_WAIT0();
        __syncthreads();
    }

    // ---- epilogue ----
#pragma unroll
    for (int half = 0; half < 2; half++) {
        int g = g0 + wg0 + quad + half * 8;
        if (g >= N_GENES) continue;
        float* base = &d_pnum[((size_t)s * N_GENES + g) * ZDIM];
#pragma unroll
        for (int nt = 0; nt < 12; nt++)
            *reinterpret_cast<float2*>(&base[nt * 8 + 2 * qi]) =
                make_float2(O[nt][half * 2 + 0], O[nt][half * 2 + 1]);
        int col = 96 + 2 * qi;
        if (col < 100)
            *reinterpret_cast<float2*>(&base[col]) =
                make_float2(O[12][half * 2 + 0], O[12][half * 2 + 1]);
        else if (col == 100)
            d_pden[s * N_GENES + g] = O[12][half * 2 + 0];
    }
}

// ---------------- K4: combine + normalize + transpose -----------------------
__global__ void k_combine(float* __restrict__ out) {
    int t = blockIdx.x * 256 + threadIdx.x;
    if (t >= N_GENES * ZDIM) return;
    int g = t / ZDIM, z = t % ZDIM;
    float num = 0.f, den = 0.f;
#pragma unroll
    for (int sp = 0; sp < NSPLIT; sp++) {
        num += d_pnum[((size_t)sp * N_GENES + g) * ZDIM + z];
        den += d_pden[sp * N_GENES + g];
    }
    out[(size_t)z * N_GENES + g] = num / den;
}

// ---------------- launch ------------------------------------------------------
extern "C" void kernel_launch(void* const* d_in, const int* in_sizes, int n_in,
                              void* d_out, int out_size) {
    (void)in_sizes; (void)n_in; (void)out_size;
    const float* rawZ   = (const float*)d_in[0];
    const float* genZ   = (const float*)d_in[1];
    const float* Grep   = (const float*)d_in[2];
    const float* gumbel = (const float*)d_in[3];
    const float* Wz1    = (const float*)d_in[4];
    const float* bz1    = (const float*)d_in[5];
    const float* Wz2    = (const float*)d_in[6];
    const float* bz2    = (const float*)d_in[7];
    const float* Wg1    = (const float*)d_in[8];
    const float* bg1    = (const float*)d_in[9];
    const float* Wg2    = (const float*)d_in[10];
    const float* bg2    = (const float*)d_in[11];
    float* out = (float*)d_out;

    static bool configured = false;
    if (!configured) {
        cudaFuncSetAttribute(k_attn, cudaFuncAttributeMaxDynamicSharedMemorySize, SMEM_BYTES);
        configured = true;
    }

    k_key<<<N_CELLS / 32, 256>>>(rawZ, Wz1, bz1, Wz2, bz2);
    k_packK<<<(N_CELLS * 16 + 255) / 256, 256>>>();
    k_packZ<<<(ZDIM * N_CELLS + 255) / 256, 256>>>(genZ);
    k_query<<<(N_GENES + 7) / 8, 256>>>(Grep, Wg1, bg1, Wg2, bg2);
    k_attn<<<dim3(GTILES, NSPLIT), 256, SMEM_BYTES>>>(gumbel);
    k_combine<<<(N_GENES * ZDIM + 255) / 256, 256>>>(out);
}

// round 8
// speedup vs baseline: 1.6604x; 1.2108x over previous
#include <cuda_runtime.h>
#include <cuda_bf16.h>
#include <cstdint>
#include <math.h>

#define N_GENES 10000
#define N_CELLS 8192
#define ZDIM    100
#define KDIM    32
#define HDIM    256

#define NSPLIT  8
#define CPB     (N_CELLS / NSPLIT)           // 1024
#define TC      32
#define NTILES  (CPB / TC)                   // 32
#define GT      128
#define GTILES  ((N_GENES + GT - 1) / GT)    // 79

// ---------------- static device scratch ------------------------------------
__device__ uint32_t d_kp[N_CELLS * 32];            // [cell][(ks*4+q)*4 + {hib0,hib1,lob0,lob1}]
__device__ float    d_query[N_GENES * KDIM];
__device__ float    d_zp[(size_t)ZDIM * N_CELLS];  // tf32, kp-paired permutation
__device__ float    d_pnum[(size_t)NSPLIT * N_GENES * ZDIM];
__device__ float    d_pden[NSPLIT * N_GENES];

// ---------------- smem layout (bytes) ---------------------------------------
#define SM_K(b)  ((b) * 6144)                // 32 rows x 192B
#define SM_Z(b)  (12288 + (b) * 19968)       // 104 rows x 192B
#define SM_E     52224                       // 128 rows x 160B
#define SMEM_BYTES 72704

__device__ __forceinline__ uint32_t smem_u32(const void* p) {
    uint32_t a;
    asm("{ .reg .u64 t; cvta.to.shared.u64 t, %1; cvt.u32.u64 %0, t; }" : "=r"(a) : "l"(p));
    return a;
}
__device__ __forceinline__ float tf32r(float x) {
    uint32_t u;
    asm("cvt.rna.tf32.f32 %0, %1;" : "=r"(u) : "f"(x));
    return __uint_as_float(u);
}
#define CP_ASYNC16(dst, src) \
    asm volatile("cp.async.cg.shared.global [%0], [%1], 16;" :: "r"(dst), "l"(src))
#define CP_COMMIT() asm volatile("cp.async.commit_group;")
#define CP_WAIT0()  asm volatile("cp.async.wait_group 0;" ::: "memory")

__device__ __forceinline__ void mma_bf16(float c[4],
                                         uint32_t a0, uint32_t a1, uint32_t a2, uint32_t a3,
                                         uint32_t b0, uint32_t b1) {
    asm volatile(
        "mma.sync.aligned.m16n8k16.row.col.f32.bf16.bf16.f32 "
        "{%0,%1,%2,%3}, {%4,%5,%6,%7}, {%8,%9}, {%0,%1,%2,%3};"
        : "+f"(c[0]), "+f"(c[1]), "+f"(c[2]), "+f"(c[3])
        : "r"(a0), "r"(a1), "r"(a2), "r"(a3), "r"(b0), "r"(b1));
}
__device__ __forceinline__ void mma_tf32(float c[4],
                                         uint32_t a0, uint32_t a1, uint32_t a2, uint32_t a3,
                                         uint32_t b0, uint32_t b1) {
    asm volatile(
        "mma.sync.aligned.m16n8k8.row.col.f32.tf32.tf32.f32 "
        "{%0,%1,%2,%3}, {%4,%5,%6,%7}, {%8,%9}, {%0,%1,%2,%3};"
        : "+f"(c[0]), "+f"(c[1]), "+f"(c[2]), "+f"(c[3])
        : "r"(a0), "r"(a1), "r"(a2), "r"(a3), "r"(b0), "r"(b1));
}
__device__ __forceinline__ float2 lds64(uint32_t addr) {
    float2 v;
    asm volatile("ld.shared.v2.f32 {%0,%1}, [%2];" : "=f"(v.x), "=f"(v.y) : "r"(addr));
    return v;
}
__device__ __forceinline__ uint4 lds128(uint32_t addr) {
    uint4 v;
    asm volatile("ld.shared.v4.u32 {%0,%1,%2,%3}, [%4];"
                 : "=r"(v.x), "=r"(v.y), "=r"(v.z), "=r"(v.w) : "r"(addr));
    return v;
}
__device__ __forceinline__ float gelu_f(float x) {
    return 0.5f * x * (1.0f + erff(x * 0.70710678118654752440f));
}
__device__ __forceinline__ uint32_t pack_bf16(float a, float b) {
    __nv_bfloat162 h = __floats2bfloat162_rn(a, b);
    return *reinterpret_cast<uint32_t*>(&h);
}

// ---------------- K0: genZ -> tf32, kp-paired permutation --------------------
__global__ void k_packZ(const float* __restrict__ genZ) {
    int tid = blockIdx.x * 256 + threadIdx.x;
    if (tid >= ZDIM * N_CELLS) return;
    int z = tid >> 13, c = tid & 8191;
    int w = c & 31, ks = w >> 3, j = w & 7;
    int pos = (ks >> 1) * 16 + (j & 3) * 4 + (ks & 1) * 2 + (j >> 2);
    d_zp[(size_t)z * N_CELLS + (c & ~31) + pos] = tf32r(genZ[tid]);
}

// ---------------- K1: key MLP -> d_kp (packed bf16 hi/lo, fused) -------------
__global__ void __launch_bounds__(256) k_key(
    const float* __restrict__ rawZ,
    const float* __restrict__ Wz1, const float* __restrict__ bz1,
    const float* __restrict__ Wz2, const float* __restrict__ bz2)
{
    __shared__ float Zs[ZDIM * 32];
    __shared__ float hs[HDIM * 33];
    const int t = threadIdx.x;
    const int c0 = blockIdx.x * 32;
    for (int i = t; i < ZDIM * 32; i += 256) {
        int z = i >> 5, c = i & 31;
        Zs[i] = rawZ[(size_t)z * N_CELLS + c0 + c];
    }
    __syncthreads();
    float acc[32];
    {
        float b = bz1[t];
#pragma unroll
        for (int c = 0; c < 32; c++) acc[c] = b;
    }
    for (int z = 0; z < ZDIM; z++) {
        float w = Wz1[z * HDIM + t];
        const float4* zr = reinterpret_cast<const float4*>(&Zs[z * 32]);
#pragma unroll
        for (int u = 0; u < 8; u++) {
            float4 v = zr[u];
            acc[4*u+0] = fmaf(w, v.x, acc[4*u+0]);
            acc[4*u+1] = fmaf(w, v.y, acc[4*u+1]);
            acc[4*u+2] = fmaf(w, v.z, acc[4*u+2]);
            acc[4*u+3] = fmaf(w, v.w, acc[4*u+3]);
        }
    }
#pragma unroll
    for (int c = 0; c < 32; c++) hs[t * 33 + c] = gelu_f(acc[c]);
    __syncthreads();

    // second layer: thread owns kdim-pair p (k=2p,2p+1) and 2 cells
    const int p = t & 15, cg = t >> 4;     // cells cg*2, cg*2+1
    const float b0 = bz2[2 * p], b1 = bz2[2 * p + 1];
    float a0c0 = b0, a0c1 = b0, a1c0 = b1, a1c1 = b1;
    for (int h = 0; h < HDIM; h++) {
        float2 wz = *reinterpret_cast<const float2*>(&Wz2[h * KDIM + 2 * p]);
        float h0 = hs[h * 33 + cg * 2];
        float h1 = hs[h * 33 + cg * 2 + 1];
        a0c0 = fmaf(wz.x, h0, a0c0);
        a0c1 = fmaf(wz.x, h1, a0c1);
        a1c0 = fmaf(wz.y, h0, a1c0);
        a1c1 = fmaf(wz.y, h1, a1c1);
    }
    // pack: ks=p>>3, j=p&7, q=j&3, h=j>>2 ; hi at word (ks*4+q)*4+h, lo at +2
    const int ks = p >> 3, j = p & 7, q = j & 3, hh = j >> 2;
    const int word = (ks * 4 + q) * 4 + hh;
#pragma unroll
    for (int cc = 0; cc < 2; cc++) {
        float x0 = cc ? a0c1 : a0c0;
        float x1 = cc ? a1c1 : a1c0;
        float h0 = __bfloat162float(__float2bfloat16(x0));
        float h1 = __bfloat162float(__float2bfloat16(x1));
        int base = (c0 + cg * 2 + cc) * 32 + word;
        d_kp[base]     = pack_bf16(h0, h1);
        d_kp[base + 2] = pack_bf16(x0 - h0, x1 - h1);
    }
}

// ---------------- K2: query MLP -> d_query[g][k] ----------------------------
__global__ void k_query(
    const float* __restrict__ Grep,
    const float* __restrict__ Wg1, const float* __restrict__ bg1,
    const float* __restrict__ Wg2, const float* __restrict__ bg2)
{
    int gene = blockIdx.x * 8 + (threadIdx.x >> 5);
    int k = threadIdx.x & 31;
    if (gene >= N_GENES) return;
    const float* grow = &Grep[(size_t)gene * 100];
    float h0 = 0.f, h1 = 0.f, h2 = 0.f, h3 = 0.f;
#pragma unroll
    for (int j = 0; j < 100; j += 4) {
        h0 = fmaf(grow[j + 0], Wg1[(j + 0) * 32 + k], h0);
        h1 = fmaf(grow[j + 1], Wg1[(j + 1) * 32 + k], h1);
        h2 = fmaf(grow[j + 2], Wg1[(j + 2) * 32 + k], h2);
        h3 = fmaf(grow[j + 3], Wg1[(j + 3) * 32 + k], h3);
    }
    float h = gelu_f(((h0 + h1) + (h2 + h3)) + bg1[k]);
    float q0 = bg2[k], q1 = 0.f, q2 = 0.f, q3 = 0.f;
#pragma unroll
    for (int j = 0; j < 32; j += 4) {
        q0 = fmaf(__shfl_sync(0xffffffffu, h, j + 0), Wg2[(j + 0) * 32 + k], q0);
        q1 = fmaf(__shfl_sync(0xffffffffu, h, j + 1), Wg2[(j + 1) * 32 + k], q1);
        q2 = fmaf(__shfl_sync(0xffffffffu, h, j + 2), Wg2[(j + 2) * 32 + k], q2);
        q3 = fmaf(__shfl_sync(0xffffffffu, h, j + 3), Wg2[(j + 3) * 32 + k], q3);
    }
    d_query[(size_t)gene * KDIM + k] = ((q0 + q1) + (q2 + q3));
}

// ---------------- K3: fused flash attention (8 warps, 16 genes/warp) ---------
__global__ void __launch_bounds__(256, 2) k_attn(const float* __restrict__ gumbel) {
    extern __shared__ __align__(16) char smem[];
    const uint32_t sb = smem_u32(smem);
    const int t = threadIdx.x;
    const int w = t >> 5, lane = t & 31;
    const int quad = lane >> 2, qi = lane & 3;
    const int g0 = blockIdx.x * GT;
    const int s = blockIdx.y;
    const int cbase = s * CPB;
    const int wg0 = w * 16;
    const int gene0 = g0 + wg0 + quad;
    const int gene1 = gene0 + 8;
    const bool ok0 = gene0 < N_GENES, ok1 = gene1 < N_GENES;
    const float SC = 0.17677669529663687f;

    // ---- Q a-frags (bf16 hi/lo) in registers ----
    uint32_t aQh[2][4], aQl[2][4];
#pragma unroll
    for (int ks = 0; ks < 2; ks++) {
#pragma unroll
        for (int r = 0; r < 4; r++) {
            int gg = (r & 1) ? gene1 : gene0;
            int kk = ks * 16 + 2 * qi + ((r & 2) ? 8 : 0);
            float x0 = 0.f, x1 = 0.f;
            if ((r & 1) ? ok1 : ok0) {
                float2 v = *reinterpret_cast<const float2*>(&d_query[(size_t)gg * 32 + kk]);
                x0 = v.x; x1 = v.y;
            }
            float h0 = __bfloat162float(__float2bfloat16(x0));
            float h1 = __bfloat162float(__float2bfloat16(x1));
            aQh[ks][r] = pack_bf16(h0, h1);
            aQl[ks][r] = pack_bf16(x0 - h0, x1 - h1);
        }
    }

    // ---- constant Z rows 100..103 in both buffers ----
    if (t < 128) {
        int z = 100 + (t >> 5), c = t & 31;
        float v = (z == 100) ? 1.0f : 0.0f;
        *reinterpret_cast<float*>(smem + SM_Z(0) + z * 192 + c * 4) = v;
        *reinterpret_cast<float*>(smem + SM_Z(1) + z * 192 + c * 4) = v;
    }

    // ---- cp.async tile 0 ----
    {
        int row = t >> 3, ch = t & 7;
        CP_ASYNC16(sb + SM_K(0) + row * 192 + ch * 16,
                   (const char*)(d_kp + (size_t)(cbase + row) * 32 + ch * 4));
        for (int idx = t; idx < 800; idx += 256) {
            int zr = idx >> 3, zc = idx & 7;
            CP_ASYNC16(sb + SM_Z(0) + zr * 192 + zc * 16,
                       (const char*)(d_zp + (size_t)zr * N_CELLS + cbase + zc * 4));
        }
    }
    CP_COMMIT();
    CP_WAIT0();
    __syncthreads();

    float O[13][4];
#pragma unroll
    for (int nt = 0; nt < 13; nt++)
#pragma unroll
        for (int e = 0; e < 4; e++) O[nt][e] = 0.0f;

    const int pos0 = (qi & 1) * 4 + (qi >> 1);   // E slot of cell 2qi

    for (int i = 0; i < NTILES; i++) {
        const int b = i & 1, nb = b ^ 1;
        const int c0 = cbase + i * TC;

        // prefetch tile i+1
        if (i + 1 < NTILES) {
            int c1 = c0 + TC;
            int row = t >> 3, ch = t & 7;
            CP_ASYNC16(sb + SM_K(nb) + row * 192 + ch * 16,
                       (const char*)(d_kp + (size_t)(c1 + row) * 32 + ch * 4));
            for (int idx = t; idx < 800; idx += 256) {
                int zr = idx >> 3, zc = idx & 7;
                CP_ASYNC16(sb + SM_Z(nb) + zr * 192 + zc * 16,
                           (const char*)(d_zp + (size_t)zr * N_CELLS + c1 + zc * 4));
            }
        }
        CP_COMMIT();

        // gumbel prefetch (this tile), streaming
        float2 gv0[4], gv1[4];
#pragma unroll
        for (int nt = 0; nt < 4; nt++) {
            gv0[nt] = ok0 ? __ldcs(reinterpret_cast<const float2*>(
                          &gumbel[(size_t)gene0 * N_CELLS + c0 + nt * 8 + 2 * qi]))
                          : make_float2(0.f, 0.f);
            gv1[nt] = ok1 ? __ldcs(reinterpret_cast<const float2*>(
                          &gumbel[(size_t)gene1 * N_CELLS + c0 + nt * 8 + 2 * qi]))
                          : make_float2(0.f, 0.f);
        }

        // ---- MMA1: scores, 3-product bf16, LDS.128 hi/lo-paired frags ----
        float C[4][4];
#pragma unroll
        for (int m = 0; m < 4; m++)
#pragma unroll
            for (int e = 0; e < 4; e++) C[m][e] = 0.0f;

        const uint32_t kbase = sb + SM_K(b);
#pragma unroll
        for (int ks = 0; ks < 2; ks++) {
            uint4 kb0 = lds128(kbase + (0 * 8 + quad) * 192 + (ks * 4 + qi) * 16);
            uint4 kb1 = lds128(kbase + (1 * 8 + quad) * 192 + (ks * 4 + qi) * 16);
            uint4 kb2 = lds128(kbase + (2 * 8 + quad) * 192 + (ks * 4 + qi) * 16);
            uint4 kb3 = lds128(kbase + (3 * 8 + quad) * 192 + (ks * 4 + qi) * 16);
            const uint32_t* ah = aQh[ks];
            const uint32_t* al = aQl[ks];
            mma_bf16(C[0], ah[0], ah[1], ah[2], ah[3], kb0.x, kb0.y);
            mma_bf16(C[1], ah[0], ah[1], ah[2], ah[3], kb1.x, kb1.y);
            mma_bf16(C[2], ah[0], ah[1], ah[2], ah[3], kb2.x, kb2.y);
            mma_bf16(C[3], ah[0], ah[1], ah[2], ah[3], kb3.x, kb3.y);
            mma_bf16(C[0], al[0], al[1], al[2], al[3], kb0.x, kb0.y);
            mma_bf16(C[1], al[0], al[1], al[2], al[3], kb1.x, kb1.y);
            mma_bf16(C[2], al[0], al[1], al[2], al[3], kb2.x, kb2.y);
            mma_bf16(C[3], al[0], al[1], al[2], al[3], kb3.x, kb3.y);
            mma_bf16(C[0], ah[0], ah[1], ah[2], ah[3], kb0.z, kb0.w);
            mma_bf16(C[1], ah[0], ah[1], ah[2], ah[3], kb1.z, kb1.w);
            mma_bf16(C[2], ah[0], ah[1], ah[2], ah[3], kb2.z, kb2.w);
            mma_bf16(C[3], ah[0], ah[1], ah[2], ah[3], kb3.z, kb3.w);
        }

        // ---- exp + gumbel -> E (tf32) into smem (160B rows) ----
        const uint32_t ebase = sb + SM_E;
#pragma unroll
        for (int nt = 0; nt < 4; nt++) {
            float e0 = tf32r(__expf(fmaf(C[nt][0], SC, gv0[nt].x)));
            float e1 = tf32r(__expf(fmaf(C[nt][1], SC, gv0[nt].y)));
            float e2 = tf32r(__expf(fmaf(C[nt][2], SC, gv1[nt].x)));
            float e3 = tf32r(__expf(fmaf(C[nt][3], SC, gv1[nt].y)));
            uint32_t r0 = ebase + (wg0 + quad) * 160 + (nt * 8 + pos0) * 4;
            uint32_t r1 = ebase + (wg0 + quad + 8) * 160 + (nt * 8 + pos0) * 4;
            asm volatile("st.shared.f32 [%0], %1;" :: "r"(r0), "f"(e0));
            asm volatile("st.shared.f32 [%0], %1;" :: "r"(r0 + 8), "f"(e1));
            asm volatile("st.shared.f32 [%0], %1;" :: "r"(r1), "f"(e2));
            asm volatile("st.shared.f32 [%0], %1;" :: "r"(r1 + 8), "f"(e3));
        }
        __syncwarp();

        // ---- MMA2: O += E(tf32) * Z(tf32); Z frags LDS.128 ks-paired ----
        const uint32_t zbase = sb + SM_Z(b);
#pragma unroll
        for (int kp = 0; kp < 2; kp++) {
            float2 e_e02 = lds64(ebase + (wg0 + quad) * 160 + ((2 * kp) * 4 + qi) * 8);
            float2 e_e13 = lds64(ebase + (wg0 + quad + 8) * 160 + ((2 * kp) * 4 + qi) * 8);
            float2 e_o02 = lds64(ebase + (wg0 + quad) * 160 + ((2 * kp + 1) * 4 + qi) * 8);
            float2 e_o13 = lds64(ebase + (wg0 + quad + 8) * 160 + ((2 * kp + 1) * 4 + qi) * 8);
            uint32_t ea0 = __float_as_uint(e_e02.x), ea2 = __float_as_uint(e_e02.y);
            uint32_t ea1 = __float_as_uint(e_e13.x), ea3 = __float_as_uint(e_e13.y);
            uint32_t oa0 = __float_as_uint(e_o02.x), oa2 = __float_as_uint(e_o02.y);
            uint32_t oa1 = __float_as_uint(e_o13.x), oa3 = __float_as_uint(e_o13.y);

            const uint32_t zoff = kp * 64 + qi * 16;
#pragma unroll
            for (int nt = 0; nt < 12; nt += 2) {
                uint4 z0 = lds128(zbase + ((nt + 0) * 8 + quad) * 192 + zoff);
                uint4 z1 = lds128(zbase + ((nt + 1) * 8 + quad) * 192 + zoff);
                mma_tf32(O[nt + 0], ea0, ea1, ea2, ea3, z0.x, z0.y);
                mma_tf32(O[nt + 1], ea0, ea1, ea2, ea3, z1.x, z1.y);
                mma_tf32(O[nt + 0], oa0, oa1, oa2, oa3, z0.z, z0.w);
                mma_tf32(O[nt + 1], oa0, oa1, oa2, oa3, z1.z, z1.w);
            }
            {
                uint4 z0 = lds128(zbase + (12 * 8 + quad) * 192 + zoff);
                mma_tf32(O[12], ea0, ea1, ea2, ea3, z0.x, z0.y);
                mma_tf32(O[12], oa0, oa1, oa2, oa3, z0.z, z0.w);
            }
        }

        CP_WAIT0();
        __syncthreads();
    }

    // ---- epilogue ----
#pragma unroll
    for (int half = 0; half < 2; half++) {
        int g = g0 + wg0 + quad + half * 8;
        if (g >= N_GENES) continue;
        float* base = &d_pnum[((size_t)s * N_GENES + g) * ZDIM];
#pragma unroll
        for (int nt = 0; nt < 12; nt++)
            *reinterpret_cast<float2*>(&base[nt * 8 + 2 * qi]) =
                make_float2(O[nt][half * 2 + 0], O[nt][half * 2 + 1]);
        int col = 96 + 2 * qi;
        if (col < 100)
            *reinterpret_cast<float2*>(&base[col]) =
                make_float2(O[12][half * 2 + 0], O[12][half * 2 + 1]);
        else if (col == 100)
            d_pden[s * N_GENES + g] = O[12][half * 2 + 0];
    }
}

// ---------------- K4: combine + normalize, coalesced transpose ---------------
__global__ void __launch_bounds__(256) k_combine(float* __restrict__ out) {
    __shared__ float tile[32][33];
    __shared__ float dinv[32];
    const int g0 = blockIdx.x * 32, z0 = blockIdx.y * 32;
    const int tx = threadIdx.x, ty = threadIdx.y;   // (32, 8)

    if (ty == 0) {
        int g = g0 + tx;
        float den = 1.0f;
        if (g < N_GENES) {
            den = 0.0f;
#pragma unroll
            for (int sp = 0; sp < NSPLIT; sp++) den += d_pden[sp * N_GENES + g];
        }
        dinv[tx] = 1.0f / den;
    }
#pragma unroll
    for (int r = 0; r < 4; r++) {
        int i = ty + r * 8;
        int g = g0 + i, z = z0 + tx;
        float num = 0.0f;
        if (g < N_GENES && z < ZDIM) {
#pragma unroll
            for (int sp = 0; sp < NSPLIT; sp++)
                num += d_pnum[((size_t)sp * N_GENES + g) * ZDIM + z];
        }
        tile[i][tx] = num;
    }
    __syncthreads();
#pragma unroll
    for (int r = 0; r < 4; r++) {
        int j = ty + r * 8;
        int z = z0 + j, g = g0 + tx;
        if (z < ZDIM && g < N_GENES)
            out[(size_t)z * N_GENES + g] = tile[tx][j] * dinv[tx];
    }
}

// ---------------- launch ------------------------------------------------------
extern "C" void kernel_launch(void* const* d_in, const int* in_sizes, int n_in,
                              void* d_out, int out_size) {
    (void)in_sizes; (void)n_in; (void)out_size;
    const float* rawZ   = (const float*)d_in[0];
    const float* genZ   = (const float*)d_in[1];
    const float* Grep   = (const float*)d_in[2];
    const float* gumbel = (const float*)d_in[3];
    const float* Wz1    = (const float*)d_in[4];
    const float* bz1    = (const float*)d_in[5];
    const float* Wz2    = (const float*)d_in[6];
    const float* bz2    = (const float*)d_in[7];
    const float* Wg1    = (const float*)d_in[8];
    const float* bg1    = (const float*)d_in[9];
    const float* Wg2    = (const float*)d_in[10];
    const float* bg2    = (const float*)d_in[11];
    float* out = (float*)d_out;

    static bool configured = false;
    if (!configured) {
        cudaFuncSetAttribute(k_attn, cudaFuncAttributeMaxDynamicSharedMemorySize, SMEM_BYTES);
        configured = true;
    }

    // launch order chosen so k_attn is the 4th launch (ncu -s captures it)
    k_packZ<<<(ZDIM * N_CELLS + 255) / 256, 256>>>(genZ);
    k_key<<<N_CELLS / 32, 256>>>(rawZ, Wz1, bz1, Wz2, bz2);
    k_query<<<(N_GENES + 7) / 8, 256>>>(Grep, Wg1, bg1, Wg2, bg2);
    k_attn<<<dim3(GTILES, NSPLIT), 256, SMEM_BYTES>>>(gumbel);
    k_combine<<<dim3((N_GENES + 31) / 32, (ZDIM + 31) / 32), dim3(32, 8)>>>(out);
}